// round 6
// baseline (speedup 1.0000x reference)
#include <cuda_runtime.h>
#include <cuda_bf16.h>
#include <cstdint>
#include <math.h>

// ---------------------------------------------------------------------------
// TransFuse on GB300 — round 6: bf16 mma.sync m16n8k16, register-masked B
// staging, multi-layer fused launches with K-split for wave balance.
//   C[m,n] = relu( sum_k A[m,k] * (W[n,k] * adj[k,n]) + bias[n] )
// ---------------------------------------------------------------------------

__device__ float g_bridge[512 * 8000];
__device__ float g_fuse[512 * 6000];
__device__ float g_h1[512 * 1024];
__device__ float g_h2[512 * 256];
__device__ float g_part[20000000];   // K-split partial scratch (80 MB)

struct LayerP {
    const float* A; const float* W; const float* adj; const float* bias;
    float* out;
    int ldA, ldW, ldAdj, ldOut;
    int N, K, KT, nt, kpc, base, count;
};
struct FusedParams { int nlayers; LayerP L[3]; };

#define STR 20   // smem row stride in u32 (bank-conflict-free for frag reads)

__device__ __forceinline__ uint32_t pack_bf16(float lo, float hi) {
    uint32_t r;
    asm("cvt.rn.bf16x2.f32 %0, %1, %2;" : "=r"(r) : "f"(hi), "f"(lo));
    return r;
}
__device__ __forceinline__ void mma_bf16(float c[4], const uint32_t a[4], const uint32_t b[2]) {
    asm volatile(
        "mma.sync.aligned.m16n8k16.row.col.f32.bf16.bf16.f32 "
        "{%0,%1,%2,%3}, {%4,%5,%6,%7}, {%8,%9}, {%0,%1,%2,%3};\n"
        : "+f"(c[0]), "+f"(c[1]), "+f"(c[2]), "+f"(c[3])
        : "r"(a[0]), "r"(a[1]), "r"(a[2]), "r"(a[3]), "r"(b[0]), "r"(b[1]));
}

// BM=128, BN=128, BK=32, 128 threads (4 warps, 2x2 of 64x64 warp tiles).
__global__ __launch_bounds__(128, 2)
void fused_gemm(FusedParams P)
{
    __shared__ uint32_t smA[2][128 * STR];
    __shared__ uint32_t smB[2][128 * STR];

    const int bid = blockIdx.x;
    int li = 0;
    #pragma unroll
    for (int i = 1; i < 3; ++i)
        if (i < P.nlayers && bid >= P.L[i].base) li = i;
    const LayerP L = P.L[li];

    const int local = bid - L.base;
    const int per_split = L.nt * 4;
    const int s   = local / per_split;
    const int rr  = local % per_split;
    const int n_t = rr / 4;          // m fastest: 4 m-CTAs of same (s,n) adjacent -> W reuse in L2
    const int m_t = rr % 4;
    const int m0 = m_t * 128;
    const int n0 = n_t * 128;
    const int kt0 = s * L.kpc;
    const int kt1 = min(L.KT, kt0 + L.kpc);

    const int t    = threadIdx.x;
    const int warp = t >> 5;
    const int lane = t & 31;
    const int wm = (warp >> 1) * 64;
    const int wn = (warp & 1) * 64;

    float acc[4][8][4];
    #pragma unroll
    for (int mt = 0; mt < 4; ++mt)
        #pragma unroll
        for (int nt = 0; nt < 8; ++nt)
            #pragma unroll
            for (int i = 0; i < 4; ++i) acc[mt][nt][i] = 0.0f;

    // staging registers (one A row + one B row per thread)
    uint32_t ap[16], bp[16];
    const int gn = n0 + t;
    const bool nok = gn < L.N;
    const float* arow = L.A + (size_t)(m0 + t) * L.ldA;
    const float* wrow = L.W + (size_t)(nok ? gn : 0) * L.ldW;
    const bool has_adj = (L.adj != nullptr);

    auto loadregs = [&](int kt) {
        const int k0 = kt * 32;
        #pragma unroll
        for (int j = 0; j < 8; ++j) {
            int k = k0 + j * 4;
            float4 v = (k < L.K) ? *reinterpret_cast<const float4*>(arow + k)
                                 : make_float4(0.f, 0.f, 0.f, 0.f);
            ap[2 * j]     = pack_bf16(v.x, v.y);
            ap[2 * j + 1] = pack_bf16(v.z, v.w);
        }
        #pragma unroll
        for (int j = 0; j < 8; ++j) {
            int k = k0 + j * 4;
            bool p = nok && k < L.K;
            float4 w = p ? *reinterpret_cast<const float4*>(wrow + k)
                         : make_float4(0.f, 0.f, 0.f, 0.f);
            if (has_adj) {
                float a0 = 0.f, a1 = 0.f, a2 = 0.f, a3 = 0.f;
                if (p) {
                    const float* ac = L.adj + (size_t)k * L.ldAdj + gn;
                    a0 = ac[0];
                    a1 = ac[(size_t)L.ldAdj];
                    a2 = ac[2 * (size_t)L.ldAdj];
                    a3 = ac[3 * (size_t)L.ldAdj];
                }
                bp[2 * j]     = pack_bf16(w.x * a0, w.y * a1);
                bp[2 * j + 1] = pack_bf16(w.z * a2, w.w * a3);
            } else {
                bp[2 * j]     = pack_bf16(w.x, w.y);
                bp[2 * j + 1] = pack_bf16(w.z, w.w);
            }
        }
    };
    auto sts = [&](int b) {
        uint32_t* Ad = smA[b] + t * STR;
        uint32_t* Bd = smB[b] + t * STR;
        #pragma unroll
        for (int c = 0; c < 4; ++c) {
            *reinterpret_cast<uint4*>(Ad + 4 * c) =
                make_uint4(ap[4*c], ap[4*c+1], ap[4*c+2], ap[4*c+3]);
            *reinterpret_cast<uint4*>(Bd + 4 * c) =
                make_uint4(bp[4*c], bp[4*c+1], bp[4*c+2], bp[4*c+3]);
        }
    };
    auto compute = [&](int b) {
        const uint32_t* As = smA[b];
        const uint32_t* Bs = smB[b];
        #pragma unroll
        for (int ks = 0; ks < 2; ++ks) {
            const int kc = ks * 8 + (lane & 3);
            uint32_t af[4][4];
            #pragma unroll
            for (int mt = 0; mt < 4; ++mt) {
                const uint32_t* p = As + (wm + mt * 16 + (lane >> 2)) * STR + kc;
                af[mt][0] = p[0];
                af[mt][1] = p[8 * STR];
                af[mt][2] = p[4];
                af[mt][3] = p[8 * STR + 4];
            }
            #pragma unroll
            for (int nt = 0; nt < 8; ++nt) {
                const uint32_t* q = Bs + (wn + nt * 8 + (lane >> 2)) * STR + kc;
                uint32_t bf[2] = { q[0], q[4] };
                #pragma unroll
                for (int mt = 0; mt < 4; ++mt)
                    mma_bf16(acc[mt][nt], af[mt], bf);
            }
        }
    };

    // pipeline
    const int nk = kt1 - kt0;
    loadregs(kt0);
    sts(0);
    __syncthreads();
    for (int i = 0; i < nk; ++i) {
        const int b = i & 1;
        if (i + 1 < nk) loadregs(kt0 + i + 1);
        compute(b);
        __syncthreads();
        if (i + 1 < nk) {
            sts(b ^ 1);
            __syncthreads();
        }
    }

    // epilogue
    float* outp = L.out + (size_t)s * 512 * L.ldOut;
    const bool has_bias = (L.bias != nullptr);
    #pragma unroll
    for (int mt = 0; mt < 4; ++mt) {
        #pragma unroll
        for (int nt = 0; nt < 8; ++nt) {
            const int m = m0 + wm + mt * 16 + (lane >> 2);
            const int n = n0 + wn + nt * 8 + (lane & 3) * 2;
            float* cr = acc[mt][nt];
            #pragma unroll
            for (int h = 0; h < 2; ++h) {
                int nn = n + h;
                if (nn < L.N) {
                    float v0 = cr[h];
                    float v1 = cr[h + 2];
                    if (has_bias) {
                        float bb = L.bias[nn];
                        v0 += bb; v1 += bb;
                        v0 = v0 > 0.f ? v0 : 0.f;
                        v1 = v1 > 0.f ? v1 : 0.f;
                    }
                    outp[(size_t)m * L.ldOut + nn] = v0;
                    outp[(size_t)(m + 8) * L.ldOut + nn] = v1;
                }
            }
        }
    }
}

// out[m, n] = relu( sum_s part[s][m, n] + bias[n] )
template <int S>
__global__ void combine_k(const float* __restrict__ part, int N,
                          const float* __restrict__ bias,
                          float* __restrict__ out, int ldOut)
{
    int i = blockIdx.x * 256 + threadIdx.x;
    if (i >= 512 * N) return;
    float v = 0.f;
    #pragma unroll
    for (int s = 0; s < S; ++s) v += part[(size_t)s * 512 * N + i];
    int m = i / N, n = i - m * N;
    v += bias[n];
    out[(size_t)m * ldOut + n] = v > 0.f ? v : 0.f;
}

__global__ void head_kernel(const float* __restrict__ h2,
                            const float* __restrict__ W_out,
                            const float* __restrict__ b_out,
                            float* __restrict__ out)
{
    int b = blockIdx.x;
    int lane = threadIdx.x;
    float s = 0.f;
    #pragma unroll
    for (int k = lane; k < 256; k += 32)
        s += h2[b * 256 + k] * W_out[k];
    #pragma unroll
    for (int o = 16; o > 0; o >>= 1)
        s += __shfl_down_sync(0xFFFFFFFFu, s, o);
    if (lane == 0)
        out[b] = 1.0f / (1.0f + expf(-(s + b_out[0])));
}

extern "C" void kernel_launch(void* const* d_in, const int* in_sizes, int n_in,
                              void* d_out, int out_size)
{
    const float* in_mat  = (const float*)d_in[0];   // [512, 28000]
    const float* adj_sg  = (const float*)d_in[1];   // [20000, 5000]
    const float* adj_gp  = (const float*)d_in[2];   // [5000, 3000]
    const float* adj_br  = (const float*)d_in[3];   // [8000, 3000]
    const float* adj_pp  = (const float*)d_in[4];   // [3000, 3000]
    const float* W_sg    = (const float*)d_in[5];
    const float* b_sg    = (const float*)d_in[6];
    const float* W_gp    = (const float*)d_in[7];
    const float* b_gp    = (const float*)d_in[8];
    const float* W_br    = (const float*)d_in[9];
    const float* b_br    = (const float*)d_in[10];
    const float* W_pp    = (const float*)d_in[11];
    const float* b_pp    = (const float*)d_in[12];
    const float* W_h1    = (const float*)d_in[13];
    const float* b_h1    = (const float*)d_in[14];
    const float* W_h2    = (const float*)d_in[15];
    const float* b_h2    = (const float*)d_in[16];
    const float* W_out   = (const float*)d_in[17];
    const float* b_out   = (const float*)d_in[18];
    float* out = (float*)d_out;

    float *bridge, *fuse, *h1, *h2, *part;
    cudaGetSymbolAddress((void**)&bridge, g_bridge);
    cudaGetSymbolAddress((void**)&fuse,   g_fuse);
    cudaGetSymbolAddress((void**)&h1,     g_h1);
    cudaGetSymbolAddress((void**)&h2,     g_h2);
    cudaGetSymbolAddress((void**)&part,   g_part);

    const size_t SNP_PART = 0;
    const size_t GEN_PART = (size_t)6 * 512 * 5000;   // 15,360,000

    // ---- phase 1: snp(S=6) + gene(S=2) + protein(S=1, final) ----
    {
        FusedParams P; P.nlayers = 3;
        // snp: K=20000, KT=625, kpc=105, nt=40 -> 960 CTAs
        P.L[0] = { in_mat + 8000, W_sg, adj_sg, nullptr, part + SNP_PART,
                   28000, 20000, 5000, 5000, 5000, 20000, 625, 40, 105, 0, 960 };
        // gene: K=5000, KT=157, kpc=79, nt=24 -> 192 CTAs
        P.L[1] = { in_mat + 3000, W_gp, adj_gp, nullptr, part + GEN_PART,
                   28000, 5000, 3000, 3000, 3000, 5000, 157, 24, 79, 960, 192 };
        // protein: K=3000, KT=94, nt=24 -> 96 CTAs, final (bias+relu)
        P.L[2] = { in_mat, W_pp, adj_pp, b_pp, fuse + 3000,
                   28000, 3000, 3000, 6000, 3000, 3000, 94, 24, 94, 1152, 96 };
        fused_gemm<<<1248, 128>>>(P);
    }
    combine_k<6><<<(512 * 5000 + 255) / 256, 256>>>(part + SNP_PART, 5000, b_sg, bridge, 8000);
    combine_k<2><<<(512 * 3000 + 255) / 256, 256>>>(part + GEN_PART, 3000, b_gp, bridge + 5000, 8000);

    // ---- phase 2: bridge (S=6) ----
    {
        FusedParams P; P.nlayers = 1;
        // bridge: K=8000, KT=250, kpc=42, nt=24 -> 576 CTAs
        P.L[0] = { bridge, W_br, adj_br, nullptr, part,
                   8000, 8000, 3000, 3000, 3000, 8000, 250, 24, 42, 0, 576 };
        fused_gemm<<<576, 128>>>(P);
    }
    combine_k<6><<<(512 * 3000 + 255) / 256, 256>>>(part, 3000, b_br, fuse, 6000);

    // ---- phase 2b: h1 dense (S=8) ----
    {
        FusedParams P; P.nlayers = 1;
        // h1: K=6000, KT=188, kpc=24, nt=8 -> 256 CTAs
        P.L[0] = { fuse, W_h1, nullptr, nullptr, part,
                   6000, 6000, 0, 1024, 1024, 6000, 188, 8, 24, 0, 256 };
        fused_gemm<<<256, 128>>>(P);
    }
    combine_k<8><<<(512 * 1024 + 255) / 256, 256>>>(part, 1024, b_h1, h1, 1024);

    // ---- phase 3: h2 dense (final) ----
    {
        FusedParams P; P.nlayers = 1;
        // h2: K=1024, KT=32, nt=2 -> 8 CTAs
        P.L[0] = { h1, W_h2, nullptr, b_h2, h2,
                   1024, 1024, 0, 256, 256, 1024, 32, 2, 32, 0, 8 };
        fused_gemm<<<8, 128>>>(P);
    }
    head_kernel<<<512, 32>>>(h2, W_out, b_out, out);
}

// round 7
// speedup vs baseline: 3.1664x; 3.1664x over previous
#include <cuda_runtime.h>
#include <cuda_bf16.h>
#include <cstdint>
#include <math.h>

// ---------------------------------------------------------------------------
// TransFuse on GB300 — round 7.
// Phase 0: streaming prepass -> masked weights in bf16 (Wb = bf16(W * adj^T)),
//          bf16 convert of dense weights and input activations.
// Phase 1+: clean dense bf16 mma.sync GEMMs, 3-stage cp.async pipeline,
//          K-split for wave balance, fp32-partial combines emitting bf16.
// ---------------------------------------------------------------------------

__device__ __nv_bfloat16 g_wb[154500000];   // packed masked/dense weights (bf16)
__device__ __nv_bfloat16 g_act[14336000];   // in_mat as bf16 [512][28000]
__device__ __nv_bfloat16 g_bridge[4096000]; // [512][8000]
__device__ __nv_bfloat16 g_fuse[3072000];   // [512][6000]
__device__ __nv_bfloat16 g_h1[524288];      // [512][1024]
__device__ __nv_bfloat16 g_h2[131072];      // [512][256]
__device__ float g_part[16000000];          // fp32 K-split partials (64 MB)

// weight offsets within g_wb
#define OFF_SG 0
#define OFF_GP 100000000
#define OFF_BR 115000000
#define OFF_PP 139000000
#define OFF_H1 148000000
#define OFF_H2 154200000

#define STR 20   // smem row stride in u32 (proven conflict-free both ways)

__device__ __forceinline__ uint32_t pack_bf16(float lo, float hi) {
    uint32_t r;
    asm("cvt.rn.bf16x2.f32 %0, %1, %2;" : "=r"(r) : "f"(hi), "f"(lo));
    return r;
}
__device__ __forceinline__ uint32_t smem_u32(const void* p) {
    uint32_t a;
    asm("{ .reg .u64 t; cvta.to.shared.u64 t, %1; cvt.u32.u64 %0, t; }" : "=r"(a) : "l"(p));
    return a;
}
__device__ __forceinline__ void cp16(uint32_t dst, const void* src, bool p) {
    int sz = p ? 16 : 0;
    asm volatile("cp.async.cg.shared.global [%0], [%1], 16, %2;\n"
                 :: "r"(dst), "l"(src), "r"(sz));
}
__device__ __forceinline__ void cp_commit() { asm volatile("cp.async.commit_group;\n"); }
template <int N_> __device__ __forceinline__ void cp_wait() {
    asm volatile("cp.async.wait_group %0;\n" :: "n"(N_));
}
__device__ __forceinline__ void mma_bf16(float c[4], const uint32_t a[4], const uint32_t b[2]) {
    asm volatile(
        "mma.sync.aligned.m16n8k16.row.col.f32.bf16.bf16.f32 "
        "{%0,%1,%2,%3}, {%4,%5,%6,%7}, {%8,%9}, {%0,%1,%2,%3};\n"
        : "+f"(c[0]), "+f"(c[1]), "+f"(c[2]), "+f"(c[3])
        : "r"(a[0]), "r"(a[1]), "r"(a[2]), "r"(a[3]), "r"(b[0]), "r"(b[1]));
}

// ---------------------------------------------------------------------------
// Prepass: Wb[n][k] = bf16( W[n][k] * adj[k][n] ).  Tile 128n x 32k per CTA.
// ---------------------------------------------------------------------------
__global__ __launch_bounds__(256)
void mask_pack(const float* __restrict__ W, const float* __restrict__ adj,
               __nv_bfloat16* __restrict__ out, int N, int K)
{
    __shared__ float adjs[32][132];
    const int k0 = blockIdx.x * 32;
    const int n0 = blockIdx.y * 128;
    const int t = threadIdx.x;

    // load adj[k0..+32][n0..+128] coalesced along n
    #pragma unroll
    for (int i = 0; i < 4; ++i) {
        int idx = t + i * 256;               // 1024 float4 chunks: 32 k x 32 n4
        int kk = idx >> 5;
        int nc = (idx & 31) * 4;
        bool p = (k0 + kk) < K && (n0 + nc) < N;     // N % 4 == 0
        float4 v = make_float4(0.f, 0.f, 0.f, 0.f);
        if (p) v = *reinterpret_cast<const float4*>(adj + (size_t)(k0 + kk) * N + n0 + nc);
        *reinterpret_cast<float4*>(&adjs[kk][nc]) = v;
    }
    __syncthreads();

    // each item: one 8-k chunk of one n-row
    #pragma unroll
    for (int i = 0; i < 2; ++i) {
        int idx = t + i * 256;               // 512 items: 128 n x 4 kc
        int n  = idx >> 2;
        int kc = idx & 3;
        int gn = n0 + n;
        int gk = k0 + kc * 8;
        if (gn >= N || gk >= K) continue;    // K % 8 == 0 -> full chunks only
        const float* wp = W + (size_t)gn * K + gk;
        float4 w0 = *reinterpret_cast<const float4*>(wp);
        float4 w1 = *reinterpret_cast<const float4*>(wp + 4);
        float m0 = adjs[kc * 8 + 0][n], m1 = adjs[kc * 8 + 1][n];
        float m2 = adjs[kc * 8 + 2][n], m3 = adjs[kc * 8 + 3][n];
        float m4 = adjs[kc * 8 + 4][n], m5 = adjs[kc * 8 + 5][n];
        float m6 = adjs[kc * 8 + 6][n], m7 = adjs[kc * 8 + 7][n];
        uint4 o;
        o.x = pack_bf16(w0.x * m0, w0.y * m1);
        o.y = pack_bf16(w0.z * m2, w0.w * m3);
        o.z = pack_bf16(w1.x * m4, w1.y * m5);
        o.w = pack_bf16(w1.z * m6, w1.w * m7);
        *reinterpret_cast<uint4*>(out + (size_t)gn * K + gk) = o;
    }
}

// fp32 -> bf16 elementwise (count % 4 == 0)
__global__ void conv_bf16(const float* __restrict__ src, __nv_bfloat16* __restrict__ dst, int n4)
{
    int i = blockIdx.x * 256 + threadIdx.x;
    if (i >= n4) return;
    float4 v = *reinterpret_cast<const float4*>(src + (size_t)i * 4);
    uint2 o;
    o.x = pack_bf16(v.x, v.y);
    o.y = pack_bf16(v.z, v.w);
    *reinterpret_cast<uint2*>(dst + (size_t)i * 4) = o;
}

// ---------------------------------------------------------------------------
// Dense bf16 GEMM: C[m,n] = sum_k A[m,k] * Wb[n,k]  (+bias, relu, bf16 if final)
// BM=128, BN=128, BK=32, 128 threads, 3-stage cp.async pipeline.
// ---------------------------------------------------------------------------
struct LayerP {
    const __nv_bfloat16* A;
    const __nv_bfloat16* W;
    const float* bias;     // null -> partial fp32 out at out + s*512*N
    void* out;             // float* (partial) or bf16* (final)
    int ldA, ldOut, N, K, KT, nt, kpc, base;
};
struct FusedParams { int nlayers; LayerP L[3]; };

__global__ __launch_bounds__(128, 2)
void fused_gemm(FusedParams P)
{
    extern __shared__ uint32_t sm[];   // 3 stages x (A 2560 + B 2560) u32

    const int bid = blockIdx.x;
    int li = 0;
    #pragma unroll
    for (int i = 1; i < 3; ++i)
        if (i < P.nlayers && bid >= P.L[i].base) li = i;
    const LayerP L = P.L[li];

    const int local = bid - L.base;
    const int per_split = L.nt * 4;
    const int s   = local / per_split;
    const int rr  = local % per_split;
    const int n_t = rr >> 2;           // m fastest -> W reuse in L2 across 4 m-CTAs
    const int m_t = rr & 3;
    const int m0 = m_t * 128;
    const int n0 = n_t * 128;
    const int kt0 = s * L.kpc;
    const int kt1 = min(L.KT, kt0 + L.kpc);
    const int nk = kt1 - kt0;

    const int t    = threadIdx.x;
    const int warp = t >> 5;
    const int lane = t & 31;
    const int wm = (warp >> 1) * 64;
    const int wn = (warp & 1) * 64;

    float acc[4][8][4];
    #pragma unroll
    for (int mt = 0; mt < 4; ++mt)
        #pragma unroll
        for (int nt = 0; nt < 8; ++nt)
            #pragma unroll
            for (int i = 0; i < 4; ++i) acc[mt][nt][i] = 0.0f;

    const __nv_bfloat16* arow = L.A + (size_t)(m0 + t) * L.ldA;
    const int gn = n0 + t;
    const bool nok = gn < L.N;
    const __nv_bfloat16* wrow = L.W + (size_t)(nok ? gn : 0) * L.K;

    const uint32_t smb = smem_u32(sm);
    const uint32_t adst = smb + t * (STR * 4);        // row t of A tile
    const uint32_t bdst = adst + 2560 * 4;            // row t of B tile

    auto issue = [&](int i) {
        const int k0 = (kt0 + i) * 32;
        const uint32_t so = (i % 3) * 5120 * 4;
        #pragma unroll
        for (int c = 0; c < 4; ++c) {
            bool pa = (k0 + c * 8) < L.K;
            cp16(adst + so + c * 16, arow + (pa ? k0 + c * 8 : 0), pa);
        }
        #pragma unroll
        for (int c = 0; c < 4; ++c) {
            bool pb = nok && (k0 + c * 8) < L.K;
            cp16(bdst + so + c * 16, wrow + (pb ? k0 + c * 8 : 0), pb);
        }
    };

    // prologue: 3 commit groups (empty if nk small)
    #pragma unroll
    for (int i = 0; i < 3; ++i) {
        if (i < nk) issue(i);
        cp_commit();
    }

    for (int i = 0; i < nk; ++i) {
        cp_wait<2>();
        __syncthreads();

        const uint32_t* As = sm + (i % 3) * 5120;
        const uint32_t* Bs = As + 2560;
        #pragma unroll
        for (int ks = 0; ks < 2; ++ks) {
            const int kc = ks * 8 + (lane & 3);
            uint32_t af[4][4];
            #pragma unroll
            for (int mt = 0; mt < 4; ++mt) {
                const uint32_t* p = As + (wm + mt * 16 + (lane >> 2)) * STR + kc;
                af[mt][0] = p[0];
                af[mt][1] = p[8 * STR];
                af[mt][2] = p[4];
                af[mt][3] = p[8 * STR + 4];
            }
            #pragma unroll
            for (int nt = 0; nt < 8; ++nt) {
                const uint32_t* q = Bs + (wn + nt * 8 + (lane >> 2)) * STR + kc;
                uint32_t bf[2] = { q[0], q[4] };
                #pragma unroll
                for (int mt = 0; mt < 4; ++mt)
                    mma_bf16(acc[mt][nt], af[mt], bf);
            }
        }
        __syncthreads();

        if (i + 3 < nk) issue(i + 3);
        cp_commit();
    }

    // epilogue
    const bool fin = (L.bias != nullptr);
    #pragma unroll
    for (int mt = 0; mt < 4; ++mt) {
        #pragma unroll
        for (int nt = 0; nt < 8; ++nt) {
            const int m = m0 + wm + mt * 16 + (lane >> 2);
            const int n = n0 + wn + nt * 8 + (lane & 3) * 2;
            if (n >= L.N) continue;      // N even -> n, n+1 both valid or neither
            float* cr = acc[mt][nt];
            if (fin) {
                float b0 = L.bias[n], b1 = L.bias[n + 1];
                float v00 = cr[0] + b0, v01 = cr[1] + b1;
                float v10 = cr[2] + b0, v11 = cr[3] + b1;
                v00 = v00 > 0.f ? v00 : 0.f;  v01 = v01 > 0.f ? v01 : 0.f;
                v10 = v10 > 0.f ? v10 : 0.f;  v11 = v11 > 0.f ? v11 : 0.f;
                __nv_bfloat16* ob = (__nv_bfloat16*)L.out;
                *reinterpret_cast<uint32_t*>(ob + (size_t)m * L.ldOut + n) = pack_bf16(v00, v01);
                *reinterpret_cast<uint32_t*>(ob + (size_t)(m + 8) * L.ldOut + n) = pack_bf16(v10, v11);
            } else {
                float* op = (float*)L.out + (size_t)s * 512 * L.N;
                op[(size_t)m * L.N + n]           = cr[0];
                op[(size_t)m * L.N + n + 1]       = cr[1];
                op[(size_t)(m + 8) * L.N + n]     = cr[2];
                op[(size_t)(m + 8) * L.N + n + 1] = cr[3];
            }
        }
    }
}

// sum S fp32 partials, +bias, relu, write bf16
template <int S>
__global__ void combine_k(const float* __restrict__ part, int N,
                          const float* __restrict__ bias,
                          __nv_bfloat16* __restrict__ out, int ldOut)
{
    int i = blockIdx.x * 256 + threadIdx.x;
    int half = 512 * (N >> 1);
    if (i >= half) return;
    int m = i / (N >> 1);
    int n = (i - m * (N >> 1)) * 2;
    size_t o = (size_t)m * N + n;
    float v0 = 0.f, v1 = 0.f;
    #pragma unroll
    for (int s = 0; s < S; ++s) {
        v0 += part[(size_t)s * 512 * N + o];
        v1 += part[(size_t)s * 512 * N + o + 1];
    }
    v0 += bias[n];     v1 += bias[n + 1];
    v0 = v0 > 0.f ? v0 : 0.f;
    v1 = v1 > 0.f ? v1 : 0.f;
    *reinterpret_cast<uint32_t*>(out + (size_t)m * ldOut + n) = pack_bf16(v0, v1);
}

// y[b] = sigmoid( dot(h2[b,:], W_out) + b_out )
__global__ void head_kernel(const __nv_bfloat16* __restrict__ h2,
                            const float* __restrict__ W_out,
                            const float* __restrict__ b_out,
                            float* __restrict__ out)
{
    int b = blockIdx.x;
    int lane = threadIdx.x;
    float s = 0.f;
    #pragma unroll
    for (int k = lane; k < 256; k += 32)
        s += __bfloat162float(h2[b * 256 + k]) * W_out[k];
    #pragma unroll
    for (int o = 16; o > 0; o >>= 1)
        s += __shfl_down_sync(0xFFFFFFFFu, s, o);
    if (lane == 0)
        out[b] = 1.0f / (1.0f + expf(-(s + b_out[0])));
}

static constexpr int GEMM_SMEM = 3 * 5120 * 4;   // 61440 B

extern "C" void kernel_launch(void* const* d_in, const int* in_sizes, int n_in,
                              void* d_out, int out_size)
{
    const float* in_mat  = (const float*)d_in[0];
    const float* adj_sg  = (const float*)d_in[1];
    const float* adj_gp  = (const float*)d_in[2];
    const float* adj_br  = (const float*)d_in[3];
    const float* adj_pp  = (const float*)d_in[4];
    const float* W_sg    = (const float*)d_in[5];
    const float* b_sg    = (const float*)d_in[6];
    const float* W_gp    = (const float*)d_in[7];
    const float* b_gp    = (const float*)d_in[8];
    const float* W_br    = (const float*)d_in[9];
    const float* b_br    = (const float*)d_in[10];
    const float* W_pp    = (const float*)d_in[11];
    const float* b_pp    = (const float*)d_in[12];
    const float* W_h1    = (const float*)d_in[13];
    const float* b_h1    = (const float*)d_in[14];
    const float* W_h2    = (const float*)d_in[15];
    const float* b_h2    = (const float*)d_in[16];
    const float* W_out   = (const float*)d_in[17];
    const float* b_out   = (const float*)d_in[18];
    float* out = (float*)d_out;

    cudaFuncSetAttribute(fused_gemm, cudaFuncAttributeMaxDynamicSharedMemorySize, GEMM_SMEM);

    __nv_bfloat16 *wb, *act, *bridge, *fuse, *h1, *h2;
    float* part;
    cudaGetSymbolAddress((void**)&wb,     g_wb);
    cudaGetSymbolAddress((void**)&act,    g_act);
    cudaGetSymbolAddress((void**)&bridge, g_bridge);
    cudaGetSymbolAddress((void**)&fuse,   g_fuse);
    cudaGetSymbolAddress((void**)&h1,     g_h1);
    cudaGetSymbolAddress((void**)&h2,     g_h2);
    cudaGetSymbolAddress((void**)&part,   g_part);

    // ---- phase 0: prepass ----
    conv_bf16<<<(14336000 / 4 + 255) / 256, 256>>>(in_mat, act, 14336000 / 4);
    conv_bf16<<<(6144000 / 4 + 255) / 256, 256>>>(W_h1, wb + OFF_H1, 6144000 / 4);
    conv_bf16<<<(262144 / 4 + 255) / 256, 256>>>(W_h2, wb + OFF_H2, 262144 / 4);
    mask_pack<<<dim3(625, 40), 256>>>(W_sg, adj_sg, wb + OFF_SG, 5000, 20000);
    mask_pack<<<dim3(157, 24), 256>>>(W_gp, adj_gp, wb + OFF_GP, 3000, 5000);
    mask_pack<<<dim3(250, 24), 256>>>(W_br, adj_br, wb + OFF_BR, 3000, 8000);
    mask_pack<<<dim3(94, 24),  256>>>(W_pp, adj_pp, wb + OFF_PP, 3000, 3000);

    const size_t PART_GP = 10240000;   // after sg's 4*512*5000

    // ---- phase 1: snp(S=4) + gene(S=2) + protein(final) ----
    {
        FusedParams P; P.nlayers = 3;
        P.L[0] = { act + 8000, wb + OFF_SG, nullptr, part,
                   28000, 5000, 5000, 20000, 625, 40, 157, 0 };
        P.L[1] = { act + 3000, wb + OFF_GP, nullptr, part + PART_GP,
                   28000, 3000, 3000, 5000, 157, 24, 79, 640 };
        P.L[2] = { act, wb + OFF_PP, b_pp, fuse + 3000,
                   28000, 6000, 3000, 3000, 94, 24, 94, 832 };
        fused_gemm<<<928, 128, GEMM_SMEM>>>(P);
    }
    combine_k<4><<<(512 * 2500 + 255) / 256, 256>>>(part, 5000, b_sg, bridge, 8000);
    combine_k<2><<<(512 * 1500 + 255) / 256, 256>>>(part + PART_GP, 3000, b_gp, bridge + 5000, 8000);

    // ---- phase 2: bridge (S=3) ----
    {
        FusedParams P; P.nlayers = 1;
        P.L[0] = { bridge, wb + OFF_BR, nullptr, part,
                   8000, 3000, 3000, 8000, 250, 24, 84, 0 };
        fused_gemm<<<288, 128, GEMM_SMEM>>>(P);
    }
    combine_k<3><<<(512 * 1500 + 255) / 256, 256>>>(part, 3000, b_br, fuse, 6000);

    // ---- phase 3: h1 (S=8) ----
    {
        FusedParams P; P.nlayers = 1;
        P.L[0] = { fuse, wb + OFF_H1, nullptr, part,
                   6000, 1024, 1024, 6000, 188, 8, 24, 0 };
        fused_gemm<<<256, 128, GEMM_SMEM>>>(P);
    }
    combine_k<8><<<(512 * 512 + 255) / 256, 256>>>(part, 1024, b_h1, h1, 1024);

    // ---- phase 4: h2 (final) + head ----
    {
        FusedParams P; P.nlayers = 1;
        P.L[0] = { h1, wb + OFF_H2, b_h2, h2,
                   1024, 256, 256, 1024, 32, 2, 32, 0 };
        fused_gemm<<<8, 128, GEMM_SMEM>>>(P);
    }
    head_kernel<<<512, 32>>>(h2, W_out, b_out, out);
}

// round 8
// speedup vs baseline: 3.1683x; 1.0006x over previous
#include <cuda_runtime.h>
#include <cuda_bf16.h>
#include <cstdint>
#include <math.h>

// ---------------------------------------------------------------------------
// TransFuse on GB300 — round 7.
// Phase 0: streaming prepass -> masked weights in bf16 (Wb = bf16(W * adj^T)),
//          bf16 convert of dense weights and input activations.
// Phase 1+: clean dense bf16 mma.sync GEMMs, 3-stage cp.async pipeline,
//          K-split for wave balance, fp32-partial combines emitting bf16.
// ---------------------------------------------------------------------------

__device__ __nv_bfloat16 g_wb[154500000];   // packed masked/dense weights (bf16)
__device__ __nv_bfloat16 g_act[14336000];   // in_mat as bf16 [512][28000]
__device__ __nv_bfloat16 g_bridge[4096000]; // [512][8000]
__device__ __nv_bfloat16 g_fuse[3072000];   // [512][6000]
__device__ __nv_bfloat16 g_h1[524288];      // [512][1024]
__device__ __nv_bfloat16 g_h2[131072];      // [512][256]
__device__ float g_part[16000000];          // fp32 K-split partials (64 MB)

// weight offsets within g_wb
#define OFF_SG 0
#define OFF_GP 100000000
#define OFF_BR 115000000
#define OFF_PP 139000000
#define OFF_H1 148000000
#define OFF_H2 154200000

#define STR 20   // smem row stride in u32 (proven conflict-free both ways)

__device__ __forceinline__ uint32_t pack_bf16(float lo, float hi) {
    uint32_t r;
    asm("cvt.rn.bf16x2.f32 %0, %1, %2;" : "=r"(r) : "f"(hi), "f"(lo));
    return r;
}
__device__ __forceinline__ uint32_t smem_u32(const void* p) {
    uint32_t a;
    asm("{ .reg .u64 t; cvta.to.shared.u64 t, %1; cvt.u32.u64 %0, t; }" : "=r"(a) : "l"(p));
    return a;
}
__device__ __forceinline__ void cp16(uint32_t dst, const void* src, bool p) {
    int sz = p ? 16 : 0;
    asm volatile("cp.async.cg.shared.global [%0], [%1], 16, %2;\n"
                 :: "r"(dst), "l"(src), "r"(sz));
}
__device__ __forceinline__ void cp_commit() { asm volatile("cp.async.commit_group;\n"); }
template <int N_> __device__ __forceinline__ void cp_wait() {
    asm volatile("cp.async.wait_group %0;\n" :: "n"(N_));
}
__device__ __forceinline__ void mma_bf16(float c[4], const uint32_t a[4], const uint32_t b[2]) {
    asm volatile(
        "mma.sync.aligned.m16n8k16.row.col.f32.bf16.bf16.f32 "
        "{%0,%1,%2,%3}, {%4,%5,%6,%7}, {%8,%9}, {%0,%1,%2,%3};\n"
        : "+f"(c[0]), "+f"(c[1]), "+f"(c[2]), "+f"(c[3])
        : "r"(a[0]), "r"(a[1]), "r"(a[2]), "r"(a[3]), "r"(b[0]), "r"(b[1]));
}

// ---------------------------------------------------------------------------
// Prepass: Wb[n][k] = bf16( W[n][k] * adj[k][n] ).  Tile 128n x 32k per CTA.
// ---------------------------------------------------------------------------
__global__ __launch_bounds__(256)
void mask_pack(const float* __restrict__ W, const float* __restrict__ adj,
               __nv_bfloat16* __restrict__ out, int N, int K)
{
    __shared__ float adjs[32][132];
    const int k0 = blockIdx.x * 32;
    const int n0 = blockIdx.y * 128;
    const int t = threadIdx.x;

    // load adj[k0..+32][n0..+128] coalesced along n
    #pragma unroll
    for (int i = 0; i < 4; ++i) {
        int idx = t + i * 256;               // 1024 float4 chunks: 32 k x 32 n4
        int kk = idx >> 5;
        int nc = (idx & 31) * 4;
        bool p = (k0 + kk) < K && (n0 + nc) < N;     // N % 4 == 0
        float4 v = make_float4(0.f, 0.f, 0.f, 0.f);
        if (p) v = *reinterpret_cast<const float4*>(adj + (size_t)(k0 + kk) * N + n0 + nc);
        *reinterpret_cast<float4*>(&adjs[kk][nc]) = v;
    }
    __syncthreads();

    // each item: one 8-k chunk of one n-row
    #pragma unroll
    for (int i = 0; i < 2; ++i) {
        int idx = t + i * 256;               // 512 items: 128 n x 4 kc
        int n  = idx >> 2;
        int kc = idx & 3;
        int gn = n0 + n;
        int gk = k0 + kc * 8;
        if (gn >= N || gk >= K) continue;    // K % 8 == 0 -> full chunks only
        const float* wp = W + (size_t)gn * K + gk;
        float4 w0 = *reinterpret_cast<const float4*>(wp);
        float4 w1 = *reinterpret_cast<const float4*>(wp + 4);
        float m0 = adjs[kc * 8 + 0][n], m1 = adjs[kc * 8 + 1][n];
        float m2 = adjs[kc * 8 + 2][n], m3 = adjs[kc * 8 + 3][n];
        float m4 = adjs[kc * 8 + 4][n], m5 = adjs[kc * 8 + 5][n];
        float m6 = adjs[kc * 8 + 6][n], m7 = adjs[kc * 8 + 7][n];
        uint4 o;
        o.x = pack_bf16(w0.x * m0, w0.y * m1);
        o.y = pack_bf16(w0.z * m2, w0.w * m3);
        o.z = pack_bf16(w1.x * m4, w1.y * m5);
        o.w = pack_bf16(w1.z * m6, w1.w * m7);
        *reinterpret_cast<uint4*>(out + (size_t)gn * K + gk) = o;
    }
}

// fp32 -> bf16 elementwise (count % 4 == 0)
__global__ void conv_bf16(const float* __restrict__ src, __nv_bfloat16* __restrict__ dst, int n4)
{
    int i = blockIdx.x * 256 + threadIdx.x;
    if (i >= n4) return;
    float4 v = *reinterpret_cast<const float4*>(src + (size_t)i * 4);
    uint2 o;
    o.x = pack_bf16(v.x, v.y);
    o.y = pack_bf16(v.z, v.w);
    *reinterpret_cast<uint2*>(dst + (size_t)i * 4) = o;
}

// ---------------------------------------------------------------------------
// Dense bf16 GEMM: C[m,n] = sum_k A[m,k] * Wb[n,k]  (+bias, relu, bf16 if final)
// BM=128, BN=128, BK=32, 128 threads, 3-stage cp.async pipeline.
// ---------------------------------------------------------------------------
struct LayerP {
    const __nv_bfloat16* A;
    const __nv_bfloat16* W;
    const float* bias;     // null -> partial fp32 out at out + s*512*N
    void* out;             // float* (partial) or bf16* (final)
    int ldA, ldOut, N, K, KT, nt, kpc, base;
};
struct FusedParams { int nlayers; LayerP L[3]; };

__global__ __launch_bounds__(128, 2)
void fused_gemm(FusedParams P)
{
    extern __shared__ uint32_t sm[];   // 3 stages x (A 2560 + B 2560) u32

    const int bid = blockIdx.x;
    int li = 0;
    #pragma unroll
    for (int i = 1; i < 3; ++i)
        if (i < P.nlayers && bid >= P.L[i].base) li = i;
    const LayerP L = P.L[li];

    const int local = bid - L.base;
    const int per_split = L.nt * 4;
    const int s   = local / per_split;
    const int rr  = local % per_split;
    const int n_t = rr >> 2;           // m fastest -> W reuse in L2 across 4 m-CTAs
    const int m_t = rr & 3;
    const int m0 = m_t * 128;
    const int n0 = n_t * 128;
    const int kt0 = s * L.kpc;
    const int kt1 = min(L.KT, kt0 + L.kpc);
    const int nk = kt1 - kt0;

    const int t    = threadIdx.x;
    const int warp = t >> 5;
    const int lane = t & 31;
    const int wm = (warp >> 1) * 64;
    const int wn = (warp & 1) * 64;

    float acc[4][8][4];
    #pragma unroll
    for (int mt = 0; mt < 4; ++mt)
        #pragma unroll
        for (int nt = 0; nt < 8; ++nt)
            #pragma unroll
            for (int i = 0; i < 4; ++i) acc[mt][nt][i] = 0.0f;

    const __nv_bfloat16* arow = L.A + (size_t)(m0 + t) * L.ldA;
    const int gn = n0 + t;
    const bool nok = gn < L.N;
    const __nv_bfloat16* wrow = L.W + (size_t)(nok ? gn : 0) * L.K;

    const uint32_t smb = smem_u32(sm);
    const uint32_t adst = smb + t * (STR * 4);        // row t of A tile
    const uint32_t bdst = adst + 2560 * 4;            // row t of B tile

    auto issue = [&](int i) {
        const int k0 = (kt0 + i) * 32;
        const uint32_t so = (i % 3) * 5120 * 4;
        #pragma unroll
        for (int c = 0; c < 4; ++c) {
            bool pa = (k0 + c * 8) < L.K;
            cp16(adst + so + c * 16, arow + (pa ? k0 + c * 8 : 0), pa);
        }
        #pragma unroll
        for (int c = 0; c < 4; ++c) {
            bool pb = nok && (k0 + c * 8) < L.K;
            cp16(bdst + so + c * 16, wrow + (pb ? k0 + c * 8 : 0), pb);
        }
    };

    // prologue: 3 commit groups (empty if nk small)
    #pragma unroll
    for (int i = 0; i < 3; ++i) {
        if (i < nk) issue(i);
        cp_commit();
    }

    for (int i = 0; i < nk; ++i) {
        cp_wait<2>();
        __syncthreads();

        const uint32_t* As = sm + (i % 3) * 5120;
        const uint32_t* Bs = As + 2560;
        #pragma unroll
        for (int ks = 0; ks < 2; ++ks) {
            const int kc = ks * 8 + (lane & 3);
            uint32_t af[4][4];
            #pragma unroll
            for (int mt = 0; mt < 4; ++mt) {
                const uint32_t* p = As + (wm + mt * 16 + (lane >> 2)) * STR + kc;
                af[mt][0] = p[0];
                af[mt][1] = p[8 * STR];
                af[mt][2] = p[4];
                af[mt][3] = p[8 * STR + 4];
            }
            #pragma unroll
            for (int nt = 0; nt < 8; ++nt) {
                const uint32_t* q = Bs + (wn + nt * 8 + (lane >> 2)) * STR + kc;
                uint32_t bf[2] = { q[0], q[4] };
                #pragma unroll
                for (int mt = 0; mt < 4; ++mt)
                    mma_bf16(acc[mt][nt], af[mt], bf);
            }
        }
        __syncthreads();

        if (i + 3 < nk) issue(i + 3);
        cp_commit();
    }

    // epilogue
    const bool fin = (L.bias != nullptr);
    #pragma unroll
    for (int mt = 0; mt < 4; ++mt) {
        #pragma unroll
        for (int nt = 0; nt < 8; ++nt) {
            const int m = m0 + wm + mt * 16 + (lane >> 2);
            const int n = n0 + wn + nt * 8 + (lane & 3) * 2;
            if (n >= L.N) continue;      // N even -> n, n+1 both valid or neither
            float* cr = acc[mt][nt];
            if (fin) {
                float b0 = L.bias[n], b1 = L.bias[n + 1];
                float v00 = cr[0] + b0, v01 = cr[1] + b1;
                float v10 = cr[2] + b0, v11 = cr[3] + b1;
                v00 = v00 > 0.f ? v00 : 0.f;  v01 = v01 > 0.f ? v01 : 0.f;
                v10 = v10 > 0.f ? v10 : 0.f;  v11 = v11 > 0.f ? v11 : 0.f;
                __nv_bfloat16* ob = (__nv_bfloat16*)L.out;
                *reinterpret_cast<uint32_t*>(ob + (size_t)m * L.ldOut + n) = pack_bf16(v00, v01);
                *reinterpret_cast<uint32_t*>(ob + (size_t)(m + 8) * L.ldOut + n) = pack_bf16(v10, v11);
            } else {
                float* op = (float*)L.out + (size_t)s * 512 * L.N;
                op[(size_t)m * L.N + n]           = cr[0];
                op[(size_t)m * L.N + n + 1]       = cr[1];
                op[(size_t)(m + 8) * L.N + n]     = cr[2];
                op[(size_t)(m + 8) * L.N + n + 1] = cr[3];
            }
        }
    }
}

// sum S fp32 partials, +bias, relu, write bf16
template <int S>
__global__ void combine_k(const float* __restrict__ part, int N,
                          const float* __restrict__ bias,
                          __nv_bfloat16* __restrict__ out, int ldOut)
{
    int i = blockIdx.x * 256 + threadIdx.x;
    int half = 512 * (N >> 1);
    if (i >= half) return;
    int m = i / (N >> 1);
    int n = (i - m * (N >> 1)) * 2;
    size_t o = (size_t)m * N + n;
    float v0 = 0.f, v1 = 0.f;
    #pragma unroll
    for (int s = 0; s < S; ++s) {
        v0 += part[(size_t)s * 512 * N + o];
        v1 += part[(size_t)s * 512 * N + o + 1];
    }
    v0 += bias[n];     v1 += bias[n + 1];
    v0 = v0 > 0.f ? v0 : 0.f;
    v1 = v1 > 0.f ? v1 : 0.f;
    *reinterpret_cast<uint32_t*>(out + (size_t)m * ldOut + n) = pack_bf16(v0, v1);
}

// y[b] = sigmoid( dot(h2[b,:], W_out) + b_out )
__global__ void head_kernel(const __nv_bfloat16* __restrict__ h2,
                            const float* __restrict__ W_out,
                            const float* __restrict__ b_out,
                            float* __restrict__ out)
{
    int b = blockIdx.x;
    int lane = threadIdx.x;
    float s = 0.f;
    #pragma unroll
    for (int k = lane; k < 256; k += 32)
        s += __bfloat162float(h2[b * 256 + k]) * W_out[k];
    #pragma unroll
    for (int o = 16; o > 0; o >>= 1)
        s += __shfl_down_sync(0xFFFFFFFFu, s, o);
    if (lane == 0)
        out[b] = 1.0f / (1.0f + expf(-(s + b_out[0])));
}

static constexpr int GEMM_SMEM = 3 * 5120 * 4;   // 61440 B

extern "C" void kernel_launch(void* const* d_in, const int* in_sizes, int n_in,
                              void* d_out, int out_size)
{
    const float* in_mat  = (const float*)d_in[0];
    const float* adj_sg  = (const float*)d_in[1];
    const float* adj_gp  = (const float*)d_in[2];
    const float* adj_br  = (const float*)d_in[3];
    const float* adj_pp  = (const float*)d_in[4];
    const float* W_sg    = (const float*)d_in[5];
    const float* b_sg    = (const float*)d_in[6];
    const float* W_gp    = (const float*)d_in[7];
    const float* b_gp    = (const float*)d_in[8];
    const float* W_br    = (const float*)d_in[9];
    const float* b_br    = (const float*)d_in[10];
    const float* W_pp    = (const float*)d_in[11];
    const float* b_pp    = (const float*)d_in[12];
    const float* W_h1    = (const float*)d_in[13];
    const float* b_h1    = (const float*)d_in[14];
    const float* W_h2    = (const float*)d_in[15];
    const float* b_h2    = (const float*)d_in[16];
    const float* W_out   = (const float*)d_in[17];
    const float* b_out   = (const float*)d_in[18];
    float* out = (float*)d_out;

    cudaFuncSetAttribute(fused_gemm, cudaFuncAttributeMaxDynamicSharedMemorySize, GEMM_SMEM);

    __nv_bfloat16 *wb, *act, *bridge, *fuse, *h1, *h2;
    float* part;
    cudaGetSymbolAddress((void**)&wb,     g_wb);
    cudaGetSymbolAddress((void**)&act,    g_act);
    cudaGetSymbolAddress((void**)&bridge, g_bridge);
    cudaGetSymbolAddress((void**)&fuse,   g_fuse);
    cudaGetSymbolAddress((void**)&h1,     g_h1);
    cudaGetSymbolAddress((void**)&h2,     g_h2);
    cudaGetSymbolAddress((void**)&part,   g_part);

    // ---- phase 0: prepass ----
    conv_bf16<<<(14336000 / 4 + 255) / 256, 256>>>(in_mat, act, 14336000 / 4);
    conv_bf16<<<(6144000 / 4 + 255) / 256, 256>>>(W_h1, wb + OFF_H1, 6144000 / 4);
    conv_bf16<<<(262144 / 4 + 255) / 256, 256>>>(W_h2, wb + OFF_H2, 262144 / 4);
    mask_pack<<<dim3(625, 40), 256>>>(W_sg, adj_sg, wb + OFF_SG, 5000, 20000);
    mask_pack<<<dim3(157, 24), 256>>>(W_gp, adj_gp, wb + OFF_GP, 3000, 5000);
    mask_pack<<<dim3(250, 24), 256>>>(W_br, adj_br, wb + OFF_BR, 3000, 8000);
    mask_pack<<<dim3(94, 24),  256>>>(W_pp, adj_pp, wb + OFF_PP, 3000, 3000);

    const size_t PART_GP = 10240000;   // after sg's 4*512*5000

    // ---- phase 1: snp(S=4) + gene(S=2) + protein(final) ----
    {
        FusedParams P; P.nlayers = 3;
        P.L[0] = { act + 8000, wb + OFF_SG, nullptr, part,
                   28000, 5000, 5000, 20000, 625, 40, 157, 0 };
        P.L[1] = { act + 3000, wb + OFF_GP, nullptr, part + PART_GP,
                   28000, 3000, 3000, 5000, 157, 24, 79, 640 };
        P.L[2] = { act, wb + OFF_PP, b_pp, fuse + 3000,
                   28000, 6000, 3000, 3000, 94, 24, 94, 832 };
        fused_gemm<<<928, 128, GEMM_SMEM>>>(P);
    }
    combine_k<4><<<(512 * 2500 + 255) / 256, 256>>>(part, 5000, b_sg, bridge, 8000);
    combine_k<2><<<(512 * 1500 + 255) / 256, 256>>>(part + PART_GP, 3000, b_gp, bridge + 5000, 8000);

    // ---- phase 2: bridge (S=3) ----
    {
        FusedParams P; P.nlayers = 1;
        P.L[0] = { bridge, wb + OFF_BR, nullptr, part,
                   8000, 3000, 3000, 8000, 250, 24, 84, 0 };
        fused_gemm<<<288, 128, GEMM_SMEM>>>(P);
    }
    combine_k<3><<<(512 * 1500 + 255) / 256, 256>>>(part, 3000, b_br, fuse, 6000);

    // ---- phase 3: h1 (S=8) ----
    {
        FusedParams P; P.nlayers = 1;
        P.L[0] = { fuse, wb + OFF_H1, nullptr, part,
                   6000, 1024, 1024, 6000, 188, 8, 24, 0 };
        fused_gemm<<<256, 128, GEMM_SMEM>>>(P);
    }
    combine_k<8><<<(512 * 512 + 255) / 256, 256>>>(part, 1024, b_h1, h1, 1024);

    // ---- phase 4: h2 (final) + head ----
    {
        FusedParams P; P.nlayers = 1;
        P.L[0] = { h1, wb + OFF_H2, b_h2, h2,
                   1024, 256, 256, 1024, 32, 2, 32, 0 };
        fused_gemm<<<8, 128, GEMM_SMEM>>>(P);
    }
    head_kernel<<<512, 32>>>(h2, W_out, b_out, out);
}

// round 9
// speedup vs baseline: 3.5676x; 1.1260x over previous
#include <cuda_runtime.h>
#include <cuda_bf16.h>
#include <cstdint>
#include <math.h>

__device__ __nv_bfloat16 g_wb[154500000];
__device__ __nv_bfloat16 g_act[14336000];
__device__ __nv_bfloat16 g_bridge[4096000];
__device__ __nv_bfloat16 g_fuse[3072000];
__device__ __nv_bfloat16 g_h1[524288];
__device__ __nv_bfloat16 g_h2[131072];
__device__ float g_part[20000000];

#define OFF_SG 0
#define OFF_GP 100000000
#define OFF_BR 115000000
#define OFF_PP 139000000
#define OFF_H1 148000000
#define OFF_H2 154200000

#define STR 20
#define STAGE_U32 5120
#define NSTAGE 4

__device__ __forceinline__ uint32_t pack_bf16(float lo, float hi) {
    uint32_t r;
    asm("cvt.rn.bf16x2.f32 %0, %1, %2;" : "=r"(r) : "f"(hi), "f"(lo));
    return r;
}
__device__ __forceinline__ uint32_t smem_u32(const void* p) {
    uint32_t a;
    asm("{ .reg .u64 t; cvta.to.shared.u64 t, %1; cvt.u32.u64 %0, t; }" : "=r"(a) : "l"(p));
    return a;
}
__device__ __forceinline__ void cp16(uint32_t dst, const void* src, bool p) {
    int sz = p ? 16 : 0;
    asm volatile("cp.async.cg.shared.global [%0], [%1], 16, %2;\n" :: "r"(dst), "l"(src), "r"(sz));
}
__device__ __forceinline__ void cp_commit() { asm volatile("cp.async.commit_group;\n"); }
template <int N_> __device__ __forceinline__ void cp_wait() {
    asm volatile("cp.async.wait_group %0;\n" :: "n"(N_));
}
__device__ __forceinline__ void ldsm4(uint32_t* r, uint32_t addr) {
    asm volatile("ldmatrix.sync.aligned.m8n8.x4.shared.b16 {%0,%1,%2,%3}, [%4];"
                 : "=r"(r[0]), "=r"(r[1]), "=r"(r[2]), "=r"(r[3]) : "r"(addr));
}
__device__ __forceinline__ void mma_bf16(float c[4], const uint32_t a[4], const uint32_t b[2]) {
    asm volatile(
        "mma.sync.aligned.m16n8k16.row.col.f32.bf16.bf16.f32 "
        "{%0,%1,%2,%3}, {%4,%5,%6,%7}, {%8,%9}, {%0,%1,%2,%3};\n"
        : "+f"(c[0]), "+f"(c[1]), "+f"(c[2]), "+f"(c[3])
        : "r"(a[0]), "r"(a[1]), "r"(a[2]), "r"(a[3]), "r"(b[0]), "r"(b[1]));
}

// ---------------- prepass (measured 85% DRAM — unchanged) ----------------
__global__ __launch_bounds__(256)
void mask_pack(const float* __restrict__ W, const float* __restrict__ adj,
               __nv_bfloat16* __restrict__ out, int N, int K)
{
    __shared__ float adjs[32][132];
    const int k0 = blockIdx.x * 32;
    const int n0 = blockIdx.y * 128;
    const int t = threadIdx.x;
    #pragma unroll
    for (int i = 0; i < 4; ++i) {
        int idx = t + i * 256;
        int kk = idx >> 5;
        int nc = (idx & 31) * 4;
        bool p = (k0 + kk) < K && (n0 + nc) < N;
        float4 v = make_float4(0.f, 0.f, 0.f, 0.f);
        if (p) v = *reinterpret_cast<const float4*>(adj + (size_t)(k0 + kk) * N + n0 + nc);
        *reinterpret_cast<float4*>(&adjs[kk][nc]) = v;
    }
    __syncthreads();
    #pragma unroll
    for (int i = 0; i < 2; ++i) {
        int idx = t + i * 256;
        int n  = idx >> 2;
        int kc = idx & 3;
        int gn = n0 + n;
        int gk = k0 + kc * 8;
        if (gn >= N || gk >= K) continue;
        const float* wp = W + (size_t)gn * K + gk;
        float4 w0 = *reinterpret_cast<const float4*>(wp);
        float4 w1 = *reinterpret_cast<const float4*>(wp + 4);
        uint4 o;
        o.x = pack_bf16(w0.x * adjs[kc*8+0][n], w0.y * adjs[kc*8+1][n]);
        o.y = pack_bf16(w0.z * adjs[kc*8+2][n], w0.w * adjs[kc*8+3][n]);
        o.z = pack_bf16(w1.x * adjs[kc*8+4][n], w1.y * adjs[kc*8+5][n]);
        o.w = pack_bf16(w1.z * adjs[kc*8+6][n], w1.w * adjs[kc*8+7][n]);
        *reinterpret_cast<uint4*>(out + (size_t)gn * K + gk) = o;
    }
}

__global__ void conv_bf16(const float* __restrict__ src, __nv_bfloat16* __restrict__ dst, int n4)
{
    int i = blockIdx.x * 256 + threadIdx.x;
    if (i >= n4) return;
    float4 v = *reinterpret_cast<const float4*>(src + (size_t)i * 4);
    uint2 o;
    o.x = pack_bf16(v.x, v.y);
    o.y = pack_bf16(v.z, v.w);
    *reinterpret_cast<uint2*>(dst + (size_t)i * 4) = o;
}

// ---------------- dense bf16 GEMM, ldmatrix + 4-stage pipeline ----------------
struct LayerP {
    const __nv_bfloat16* A;
    const __nv_bfloat16* W;
    const float* bias;   // null -> fp32 partial at out + s*512*N
    void* out;
    int ldA, ldOut, N, K, KT, nt, kpc, base;
};
struct FusedParams { int nlayers; LayerP L[3]; };

__global__ __launch_bounds__(128, 2)
void fused_gemm(FusedParams P)
{
    extern __shared__ uint32_t sm[];   // NSTAGE * STAGE_U32

    const int bid = blockIdx.x;
    int li = 0;
    #pragma unroll
    for (int i = 1; i < 3; ++i)
        if (i < P.nlayers && bid >= P.L[i].base) li = i;
    const LayerP L = P.L[li];

    const int local = bid - L.base;
    const int per_split = L.nt * 4;
    const int s   = local / per_split;
    const int rr  = local % per_split;
    const int n_t = rr >> 2;
    const int m_t = rr & 3;
    const int m0 = m_t * 128;
    const int n0 = n_t * 128;
    const int kt0 = s * L.kpc;
    const int kt1 = min(L.KT, kt0 + L.kpc);
    const int nk = kt1 - kt0;

    const int t    = threadIdx.x;
    const int warp = t >> 5;
    const int lane = t & 31;
    const int wm = (warp >> 1) * 64;
    const int wn = (warp & 1) * 64;

    float acc[4][8][4];
    #pragma unroll
    for (int mt = 0; mt < 4; ++mt)
        #pragma unroll
        for (int nt = 0; nt < 8; ++nt)
            #pragma unroll
            for (int i = 0; i < 4; ++i) acc[mt][nt][i] = 0.0f;

    const __nv_bfloat16* arow = L.A + (size_t)(m0 + t) * L.ldA;
    const int gn = n0 + t;
    const bool nok = gn < L.N;
    const __nv_bfloat16* wrow = L.W + (size_t)(nok ? gn : 0) * L.K;

    const uint32_t smb = smem_u32(sm);
    const uint32_t adst = smb + t * (STR * 4);
    const uint32_t bdst = adst + 2560 * 4;

    // ldmatrix lane addressing (byte offsets within a stage)
    const int lrA = (lane & 7) | (((lane >> 3) & 1) << 3);   // A: {m0-7,m8-15}x{k0,k8}
    const int lcA = (lane >> 4) * 4;
    const uint32_t aln = (uint32_t)((wm + lrA) * STR + lcA) * 4;
    const int lrB = (lane & 7) | (((lane >> 4) & 1) << 3);   // B: {n0-7:k0,k8; n8-15:k0,k8}
    const int lcB = ((lane >> 3) & 1) * 4;
    const uint32_t bln = (uint32_t)((wn + lrB) * STR + lcB) * 4 + 2560 * 4;

    auto issue = [&](int i) {
        const int k0 = (kt0 + i) * 32;
        const uint32_t so = (uint32_t)(i & 3) * (STAGE_U32 * 4);
        #pragma unroll
        for (int c = 0; c < 4; ++c) {
            bool pa = (k0 + c * 8) < L.K;
            cp16(adst + so + c * 16, arow + (pa ? k0 + c * 8 : 0), pa);
        }
        #pragma unroll
        for (int c = 0; c < 4; ++c) {
            bool pb = nok && (k0 + c * 8) < L.K;
            cp16(bdst + so + c * 16, wrow + (pb ? k0 + c * 8 : 0), pb);
        }
    };

    #pragma unroll
    for (int i = 0; i < 3; ++i) {
        if (i < nk) issue(i);
        cp_commit();
    }

    for (int i = 0; i < nk; ++i) {
        cp_wait<2>();
        __syncthreads();
        // buffer (i+3)&3 was computed in iter i-1; the barrier above protects it
        if (i + 3 < nk) issue(i + 3);
        cp_commit();

        const uint32_t stage = (uint32_t)(i & 3) * (STAGE_U32 * 4);
        const uint32_t aB = smb + stage + aln;
        const uint32_t bB = smb + stage + bln;

        #pragma unroll
        for (int ks = 0; ks < 2; ++ks) {
            uint32_t af[4][4];
            #pragma unroll
            for (int mt = 0; mt < 4; ++mt)
                ldsm4(af[mt], aB + (uint32_t)(mt * 16 * STR + ks * 8) * 4);
            uint32_t bv[4][4];
            #pragma unroll
            for (int p = 0; p < 4; ++p)
                ldsm4(bv[p], bB + (uint32_t)(p * 16 * STR + ks * 8) * 4);
            #pragma unroll
            for (int p = 0; p < 4; ++p) {
                uint32_t b0[2] = { bv[p][0], bv[p][1] };   // n(16p)+0..7
                uint32_t b1[2] = { bv[p][2], bv[p][3] };   // n(16p)+8..15
                #pragma unroll
                for (int mt = 0; mt < 4; ++mt) {
                    mma_bf16(acc[mt][2 * p],     af[mt], b0);
                    mma_bf16(acc[mt][2 * p + 1], af[mt], b1);
                }
            }
        }
    }

    const bool fin = (L.bias != nullptr);
    #pragma unroll
    for (int mt = 0; mt < 4; ++mt) {
        #pragma unroll
        for (int nt = 0; nt < 8; ++nt) {
            const int m = m0 + wm + mt * 16 + (lane >> 2);
            const int n = n0 + wn + nt * 8 + (lane & 3) * 2;
            if (n >= L.N) continue;
            float* cr = acc[mt][nt];
            if (fin) {
                float b0 = L.bias[n], b1 = L.bias[n + 1];
                float v00 = cr[0] + b0, v01 = cr[1] + b1;
                float v10 = cr[2] + b0, v11 = cr[3] + b1;
                v00 = v00 > 0.f ? v00 : 0.f;  v01 = v01 > 0.f ? v01 : 0.f;
                v10 = v10 > 0.f ? v10 : 0.f;  v11 = v11 > 0.f ? v11 : 0.f;
                __nv_bfloat16* ob = (__nv_bfloat16*)L.out;
                *reinterpret_cast<uint32_t*>(ob + (size_t)m * L.ldOut + n) = pack_bf16(v00, v01);
                *reinterpret_cast<uint32_t*>(ob + (size_t)(m + 8) * L.ldOut + n) = pack_bf16(v10, v11);
            } else {
                float* op = (float*)L.out + (size_t)s * 512 * L.N;
                op[(size_t)m * L.N + n]           = cr[0];
                op[(size_t)m * L.N + n + 1]       = cr[1];
                op[(size_t)(m + 8) * L.N + n]     = cr[2];
                op[(size_t)(m + 8) * L.N + n + 1] = cr[3];
            }
        }
    }
}

template <int S>
__global__ void combine_k(const float* __restrict__ part, int N,
                          const float* __restrict__ bias,
                          __nv_bfloat16* __restrict__ out, int ldOut)
{
    int i = blockIdx.x * 256 + threadIdx.x;
    int half = 512 * (N >> 1);
    if (i >= half) return;
    int m = i / (N >> 1);
    int n = (i - m * (N >> 1)) * 2;
    size_t o = (size_t)m * N + n;
    float v0 = 0.f, v1 = 0.f;
    #pragma unroll
    for (int s = 0; s < S; ++s) {
        v0 += part[(size_t)s * 512 * N + o];
        v1 += part[(size_t)s * 512 * N + o + 1];
    }
    v0 += bias[n];     v1 += bias[n + 1];
    v0 = v0 > 0.f ? v0 : 0.f;
    v1 = v1 > 0.f ? v1 : 0.f;
    *reinterpret_cast<uint32_t*>(out + (size_t)m * ldOut + n) = pack_bf16(v0, v1);
}

__global__ void head_kernel(const __nv_bfloat16* __restrict__ h2,
                            const float* __restrict__ W_out,
                            const float* __restrict__ b_out,
                            float* __restrict__ out)
{
    int b = blockIdx.x;
    int lane = threadIdx.x;
    float s = 0.f;
    #pragma unroll
    for (int k = lane; k < 256; k += 32)
        s += __bfloat162float(h2[b * 256 + k]) * W_out[k];
    #pragma unroll
    for (int o = 16; o > 0; o >>= 1)
        s += __shfl_down_sync(0xFFFFFFFFu, s, o);
    if (lane == 0)
        out[b] = 1.0f / (1.0f + expf(-(s + b_out[0])));
}

static constexpr int GEMM_SMEM = NSTAGE * STAGE_U32 * 4;   // 81920

extern "C" void kernel_launch(void* const* d_in, const int* in_sizes, int n_in,
                              void* d_out, int out_size)
{
    const float* in_mat  = (const float*)d_in[0];
    const float* adj_sg  = (const float*)d_in[1];
    const float* adj_gp  = (const float*)d_in[2];
    const float* adj_br  = (const float*)d_in[3];
    const float* adj_pp  = (const float*)d_in[4];
    const float* W_sg    = (const float*)d_in[5];
    const float* b_sg    = (const float*)d_in[6];
    const float* W_gp    = (const float*)d_in[7];
    const float* b_gp    = (const float*)d_in[8];
    const float* W_br    = (const float*)d_in[9];
    const float* b_br    = (const float*)d_in[10];
    const float* W_pp    = (const float*)d_in[11];
    const float* b_pp    = (const float*)d_in[12];
    const float* W_h1    = (const float*)d_in[13];
    const float* b_h1    = (const float*)d_in[14];
    const float* W_h2    = (const float*)d_in[15];
    const float* b_h2    = (const float*)d_in[16];
    const float* W_out   = (const float*)d_in[17];
    const float* b_out   = (const float*)d_in[18];
    float* out = (float*)d_out;

    cudaFuncSetAttribute(fused_gemm, cudaFuncAttributeMaxDynamicSharedMemorySize, GEMM_SMEM);

    __nv_bfloat16 *wb, *act, *bridge, *fuse, *h1, *h2;
    float* part;
    cudaGetSymbolAddress((void**)&wb,     g_wb);
    cudaGetSymbolAddress((void**)&act,    g_act);
    cudaGetSymbolAddress((void**)&bridge, g_bridge);
    cudaGetSymbolAddress((void**)&fuse,   g_fuse);
    cudaGetSymbolAddress((void**)&h1,     g_h1);
    cudaGetSymbolAddress((void**)&h2,     g_h2);
    cudaGetSymbolAddress((void**)&part,   g_part);

    // phase 0: prepass
    conv_bf16<<<(14336000 / 4 + 255) / 256, 256>>>(in_mat, act, 14336000 / 4);
    conv_bf16<<<(6144000 / 4 + 255) / 256, 256>>>(W_h1, wb + OFF_H1, 6144000 / 4);
    conv_bf16<<<(262144 / 4 + 255) / 256, 256>>>(W_h2, wb + OFF_H2, 262144 / 4);
    mask_pack<<<dim3(625, 40), 256>>>(W_sg, adj_sg, wb + OFF_SG, 5000, 20000);
    mask_pack<<<dim3(157, 24), 256>>>(W_gp, adj_gp, wb + OFF_GP, 3000, 5000);
    mask_pack<<<dim3(250, 24), 256>>>(W_br, adj_br, wb + OFF_BR, 3000, 8000);
    mask_pack<<<dim3(94, 24),  256>>>(W_pp, adj_pp, wb + OFF_PP, 3000, 3000);

    const size_t PART_GP = 15360000;   // after sg's 6*512*5000

    // phase 1: snp(S=6) + gene(S=2) + protein(final)
    {
        FusedParams P; P.nlayers = 3;
        P.L[0] = { act + 8000, wb + OFF_SG, nullptr, part,
                   28000, 5000, 5000, 20000, 625, 40, 105, 0 };
        P.L[1] = { act + 3000, wb + OFF_GP, nullptr, part + PART_GP,
                   28000, 3000, 3000, 5000, 157, 24, 79, 960 };
        P.L[2] = { act, wb + OFF_PP, b_pp, fuse + 3000,
                   28000, 6000, 3000, 3000, 94, 24, 94, 1152 };
        fused_gemm<<<1248, 128, GEMM_SMEM>>>(P);
    }
    combine_k<6><<<(512 * 2500 + 255) / 256, 256>>>(part, 5000, b_sg, bridge, 8000);
    combine_k<2><<<(512 * 1500 + 255) / 256, 256>>>(part + PART_GP, 3000, b_gp, bridge + 5000, 8000);

    // phase 2: bridge (S=3)
    {
        FusedParams P; P.nlayers = 1;
        P.L[0] = { bridge, wb + OFF_BR, nullptr, part,
                   8000, 3000, 3000, 8000, 250, 24, 84, 0 };
        fused_gemm<<<288, 128, GEMM_SMEM>>>(P);
    }
    combine_k<3><<<(512 * 1500 + 255) / 256, 256>>>(part, 3000, b_br, fuse, 6000);

    // phase 3: h1 (S=8)
    {
        FusedParams P; P.nlayers = 1;
        P.L[0] = { fuse, wb + OFF_H1, nullptr, part,
                   6000, 1024, 1024, 6000, 188, 8, 24, 0 };
        fused_gemm<<<256, 128, GEMM_SMEM>>>(P);
    }
    combine_k<8><<<(512 * 512 + 255) / 256, 256>>>(part, 1024, b_h1, h1, 1024);

    // phase 4: h2 (final) + head
    {
        FusedParams P; P.nlayers = 1;
        P.L[0] = { h1, wb + OFF_H2, b_h2, h2,
                   1024, 256, 256, 1024, 32, 2, 32, 0 };
        fused_gemm<<<8, 128, GEMM_SMEM>>>(P);
    }
    head_kernel<<<512, 32>>>(h2, W_out, b_out, out);
}